// round 5
// baseline (speedup 1.0000x reference)
#include <cuda_runtime.h>
#include <stdint.h>

#define BB 16
#define NN 2048
#define KK 20
#define ROWS (BB * NN)
#define CAP 128              // per-row candidate buffer capacity
#define LSTRIDE 512          // adjacency list entries per row (20 direct + transpose)
#define TCAP (LSTRIDE - KK)
#define THBITS_F 1.8f
#define PREF 1.79985f        // 1.8 - 1e-4 with margin

// ---- scratch (static __device__ — no allocations allowed) ----
__device__ unsigned long long g_candK[(size_t)ROWS * CAP]; // (doped<<11)|(2047-col)
__device__ int   g_ccnt[ROWS];                             // candidate counters
__device__ unsigned long long g_list[(size_t)ROWS * LSTRIDE]; // (col<<32)|bits(v)
__device__ int   g_tcnt[ROWS];                             // transpose counters
__device__ float g_dinv[ROWS];

// ---------------------------------------------------------------------------
// Pure streaming pass: one float4 of A per thread, no smem, no barriers.
// Survivors of the doped>1.8 threshold go to the per-row candidate buffer.
__global__ __launch_bounds__(256) void k_stream(const float* __restrict__ A,
                                                const float* __restrict__ Noise) {
    const size_t idx = (size_t)blockIdx.x * 256 + threadIdx.x;   // float4 index
    const float4 a   = ((const float4*)A)[idx];
    const int row    = (int)(idx >> 9);            // 512 float4 per row
    const int col0   = ((int)idx & 511) * 4;
    const size_t base = (size_t)row << 11;
    const uint32_t TH = __float_as_uint(THBITS_F);
    const float aa[4] = {a.x, a.y, a.z, a.w};
#pragma unroll
    for (int e = 0; e < 4; e++) {
        if (aa[e] > PREF) {
            float n = __ldg(Noise + base + col0 + e);
            float d = __fadd_rn(aa[e], __fmul_rn(n, 1e-4f));
            uint32_t dbits = __float_as_uint(d);
            if (dbits > TH) {
                int p = atomicAdd(&g_ccnt[row], 1);
                if (p < CAP)
                    g_candK[(size_t)row * CAP + p] =
                        ((unsigned long long)dbits << 11)
                      | (unsigned long long)(2047 - (col0 + e));
            }
        }
    }
}

// ---------------------------------------------------------------------------
// Block per row: exact top-K rank-count over the candidates. Winners reload
// their relu value from A (20 loads/row). Fallback (cnt<K or cnt>CAP — both
// astronomically rare) rebuilds all 2048 keys exactly from A+Noise.
__global__ __launch_bounds__(256) void k_select(const float* __restrict__ A,
                                                const float* __restrict__ Noise) {
    const int row = blockIdx.x;
    const int tid = threadIdx.x;
    const int b   = row >> 11;
    const size_t base = (size_t)row << 11;

    __shared__ unsigned long long sK[NN];
    __shared__ uint32_t s_kslot;
    if (tid == 0) s_kslot = 0;

    int cnt = g_ccnt[row];
    uint32_t M;
    if (cnt >= KK && cnt <= CAP) {
        // normal path: candidates already in global buffer
        for (int i = tid; i < cnt; i += 256)
            sK[i] = g_candK[(size_t)row * CAP + i];
        M = (uint32_t)cnt;
    } else {
        // exact fallback: rebuild every key for this row
        const float4* a4 = (const float4*)(A + base);
        const float4* n4 = (const float4*)(Noise + base);
#pragma unroll
        for (int h = 0; h < 2; h++) {
            float4 av = a4[h * 256 + tid];
            float4 nv = n4[h * 256 + tid];
            float aa[4] = {av.x, av.y, av.z, av.w};
            float no[4] = {nv.x, nv.y, nv.z, nv.w};
            int c0 = h * 1024 + tid * 4;
#pragma unroll
            for (int e = 0; e < 4; e++) {
                float r = fmaxf(aa[e], 0.0f);
                float d = __fadd_rn(r, __fmul_rn(no[e], 1e-4f));
                sK[c0 + e] =
                    ((unsigned long long)__float_as_uint(d) << 11)
                  | (unsigned long long)(2047 - (c0 + e));
            }
        }
        M = NN;
    }
    __syncthreads();

    // parallel rank-count; keys are distinct so exactly KK winners
    for (uint32_t i = tid; i < M; i += 256) {
        const unsigned long long key = sK[i];
        uint32_t rank = 0;
        for (uint32_t q = 0; q < M; q++)
            rank += (sK[q] > key);
        if (rank < KK) {
            int   col = 2047 - (int)(key & 2047u);
            float r   = fmaxf(__ldg(A + base + col), 0.0f);   // exact relu value
            unsigned long long entry =
                ((unsigned long long)col << 32)
              | (unsigned long long)__float_as_uint(r);
            uint32_t p = atomicAdd(&s_kslot, 1u);
            g_list[(size_t)row * LSTRIDE + p] = entry;        // direct slot
            int jrow = b * NN + col;                          // transpose entry
            uint32_t t = atomicAdd((unsigned int*)&g_tcnt[jrow], 1u);
            if (t < TCAP)
                g_list[(size_t)jrow * LSTRIDE + KK + t] =
                    ((unsigned long long)(row & 2047) << 32)
                  | (unsigned long long)__float_as_uint(r);
        }
    }
}

// ---------------------------------------------------------------------------
// Warp per row: d_i = 1 + 0.5 * sum(list values); dinv = rsqrt(d_i).
__global__ __launch_bounds__(256) void k_deg() {
    int warp = (blockIdx.x * 256 + threadIdx.x) >> 5;
    int lane = threadIdx.x & 31;
    if (warp >= ROWS) return;
    int tc = g_tcnt[warp]; if (tc > TCAP) tc = TCAP;
    int n  = KK + tc;
    float s = 0.0f;
    const unsigned long long* lst = g_list + (size_t)warp * LSTRIDE;
    for (int i = lane; i < n; i += 32)
        s += __uint_as_float((uint32_t)lst[i]);
#pragma unroll
    for (int off = 16; off; off >>= 1)
        s += __shfl_down_sync(0xffffffffu, s, off);
    if (lane == 0)
        g_dinv[warp] = rsqrtf(fmaf(0.5f, s, 1.0f));
}

// ---------------------------------------------------------------------------
// Block per row: zero smem row, scatter weighted list entries + diagonal,
// stream dense row out; also re-zeroes this row's counters for the next call.
__global__ __launch_bounds__(256) void k_writer(float* __restrict__ out) {
    const int row = blockIdx.x;
    const int tid = threadIdx.x;
    const int b   = row >> 11;

    __shared__ float srow[NN];
    float4* s4 = (float4*)srow;
    s4[tid]       = make_float4(0.f, 0.f, 0.f, 0.f);
    s4[256 + tid] = make_float4(0.f, 0.f, 0.f, 0.f);

    const float di = g_dinv[row];
    int tc = g_tcnt[row]; if (tc > TCAP) tc = TCAP;
    const int n = KK + tc;
    __syncthreads();

    const unsigned long long* lst = g_list + (size_t)row * LSTRIDE;
    for (int t = tid; t < n; t += 256) {
        unsigned long long e = lst[t];
        int   col = (int)(e >> 32);
        float v   = __uint_as_float((uint32_t)e);
        float w   = 0.5f * v * di * g_dinv[b * NN + col];
        atomicAdd(&srow[col], w);
    }
    if (tid == 0) atomicAdd(&srow[row & 2047], di * di);
    __syncthreads();

    float4* o4 = (float4*)(out + ((size_t)row << 11));
    o4[tid]       = s4[tid];
    o4[256 + tid] = s4[256 + tid];

    // counters must be zero at entry of the next call (static init covers #1)
    if (tid == 0) g_tcnt[row] = 0;
    if (tid == 1) g_ccnt[row] = 0;
}

// ---------------------------------------------------------------------------
extern "C" void kernel_launch(void* const* d_in, const int* in_sizes, int n_in,
                              void* d_out, int out_size) {
    const float* A     = (const float*)d_in[0];
    const float* Noise = (const float*)d_in[1];
    float* out = (float*)d_out;

    k_stream<<<(BB * NN * NN / 4) / 256, 256>>>(A, Noise);
    k_select<<<ROWS, 256>>>(A, Noise);
    k_deg   <<<(ROWS * 32 + 255) / 256, 256>>>();
    k_writer<<<ROWS, 256>>>(out);
}

// round 6
// speedup vs baseline: 1.7865x; 1.7865x over previous
#include <cuda_runtime.h>
#include <stdint.h>

#define BB 16
#define NN 2048
#define KK 20
#define ROWS (BB * NN)
#define LSTRIDE 512          // adjacency entries per row (20 direct + transpose)
#define TCAP (LSTRIDE - KK)
#define PREF 1.79985f        // 1.8 - 1e-4 with margin

// ---- scratch (static __device__ — no allocations allowed) ----
__device__ unsigned long long g_list[(size_t)ROWS * LSTRIDE]; // (col<<32)|bits(v)
__device__ int   g_tcnt[ROWS];   // transpose counters (zero-init; writer re-zeroes)
__device__ float g_dinv[ROWS];

// ---------------------------------------------------------------------------
// One block per row. Streams A (two float4/thread); noise fetched only for
// elements whose relu could clear the 1.8 doped threshold (~3.6%). Exact
// top-K via parallel rank-count with jax's lowest-index tie-break
// (key = doped_bits<<11 | (2047-col)); accept-all fallback if < K survive.
// Winners reload their relu value from A (L2-hot) — no value smem array.
__global__ __launch_bounds__(256) void k_topk(const float* __restrict__ A,
                                              const float* __restrict__ Noise) {
    const int row  = blockIdx.x;       // b * NN + i
    const int tid  = threadIdx.x;
    const int b    = row >> 11;
    const size_t base = (size_t)row << 11;

    __shared__ unsigned long long sK[NN];
    __shared__ uint32_t s_cnt, s_kslot;
    if (tid == 0) { s_cnt = 0; s_kslot = 0; }
    __syncthreads();

    const float4* a4 = (const float4*)(A + base);
    float4 av  = a4[tid];
    float4 av2 = a4[256 + tid];
    const uint32_t TH = __float_as_uint(1.8f);

    {
        float f[8] = {av.x, av.y, av.z, av.w, av2.x, av2.y, av2.z, av2.w};
#pragma unroll
        for (int e = 0; e < 8; e++) {
            if (f[e] > PREF) {
                int col = (e < 4) ? (tid * 4 + e) : (1024 + tid * 4 + (e - 4));
                float n = __ldg(Noise + base + col);
                float d = __fadd_rn(f[e], __fmul_rn(n, 1e-4f));
                uint32_t dbits = __float_as_uint(d);
                if (dbits > TH) {
                    uint32_t p = atomicAdd(&s_cnt, 1u);
                    sK[p] = ((unsigned long long)dbits << 11)
                          | (unsigned long long)(2047 - col);
                }
            }
        }
    }
    __syncthreads();
    uint32_t M = s_cnt;

    if (M < KK) {
        // rare exact fallback: rebuild all 2048 keys (noise row loaded in full)
        const float4* n4 = (const float4*)(Noise + base);
        float4 nv  = n4[tid];
        float4 nv2 = n4[256 + tid];
        float f[8]  = {av.x, av.y, av.z, av.w, av2.x, av2.y, av2.z, av2.w};
        float no[8] = {nv.x, nv.y, nv.z, nv.w, nv2.x, nv2.y, nv2.z, nv2.w};
#pragma unroll
        for (int e = 0; e < 8; e++) {
            int col = (e < 4) ? (tid * 4 + e) : (1024 + tid * 4 + (e - 4));
            float r = fmaxf(f[e], 0.0f);
            float d = __fadd_rn(r, __fmul_rn(no[e], 1e-4f));
            sK[col] = ((unsigned long long)__float_as_uint(d) << 11)
                    | (unsigned long long)(2047 - col);
        }
        __syncthreads();
        M = NN;
    }

    // parallel rank-count; keys distinct -> exactly KK winners
    for (uint32_t i = tid; i < M; i += 256) {
        const unsigned long long key = sK[i];
        uint32_t rank = 0;
        for (uint32_t q = 0; q < M; q++)
            rank += (sK[q] > key);
        if (rank < KK) {
            int   col = 2047 - (int)(key & 2047u);
            float r   = fmaxf(__ldg(A + base + col), 0.0f);  // exact relu value
            unsigned long long entry =
                ((unsigned long long)col << 32)
              | (unsigned long long)__float_as_uint(r);
            uint32_t p = atomicAdd(&s_kslot, 1u);
            g_list[(size_t)row * LSTRIDE + p] = entry;        // direct slot
            int jrow = b * NN + col;                          // transpose entry
            uint32_t t = atomicAdd((unsigned int*)&g_tcnt[jrow], 1u);
            if (t < TCAP)
                g_list[(size_t)jrow * LSTRIDE + KK + t] =
                    ((unsigned long long)(row & 2047) << 32)
                  | (unsigned long long)__float_as_uint(r);
        }
    }
}

// ---------------------------------------------------------------------------
// Warp per row: d_i = 1 + 0.5 * sum(list values); self-loops double-count
// exactly as rowsum+colsum does. dinv = rsqrt(d_i).
__global__ __launch_bounds__(256) void k_deg() {
    int warp = (blockIdx.x * 256 + threadIdx.x) >> 5;
    int lane = threadIdx.x & 31;
    if (warp >= ROWS) return;
    int tc = g_tcnt[warp]; if (tc > TCAP) tc = TCAP;
    int n  = KK + tc;
    float s = 0.0f;
    const unsigned long long* lst = g_list + (size_t)warp * LSTRIDE;
    for (int i = lane; i < n; i += 32)
        s += __uint_as_float((uint32_t)lst[i]);
#pragma unroll
    for (int off = 16; off; off >>= 1)
        s += __shfl_down_sync(0xffffffffu, s, off);
    if (lane == 0)
        g_dinv[warp] = rsqrtf(fmaf(0.5f, s, 1.0f));
}

// ---------------------------------------------------------------------------
// Block per row: zero smem row, scatter weighted entries + diagonal, stream
// the dense row out with evict-first stores; re-zero this row's counter.
__global__ __launch_bounds__(256) void k_writer(float* __restrict__ out) {
    const int row = blockIdx.x;
    const int tid = threadIdx.x;
    const int b   = row >> 11;

    __shared__ float srow[NN];
    float4* s4 = (float4*)srow;
    s4[tid]       = make_float4(0.f, 0.f, 0.f, 0.f);
    s4[256 + tid] = make_float4(0.f, 0.f, 0.f, 0.f);

    const float di = g_dinv[row];
    int tc = g_tcnt[row]; if (tc > TCAP) tc = TCAP;
    const int n = KK + tc;
    __syncthreads();

    const unsigned long long* lst = g_list + (size_t)row * LSTRIDE;
    for (int t = tid; t < n; t += 256) {
        unsigned long long e = lst[t];
        int   col = (int)(e >> 32);
        float v   = __uint_as_float((uint32_t)e);
        float w   = 0.5f * v * di * __ldg(&g_dinv[b * NN + col]);
        atomicAdd(&srow[col], w);
    }
    if (tid == 0) atomicAdd(&srow[row & 2047], di * di);
    __syncthreads();

    float4* o4 = (float4*)(out + ((size_t)row << 11));
    __stcs(&o4[tid],       s4[tid]);
    __stcs(&o4[256 + tid], s4[256 + tid]);

    if (tid == 0) g_tcnt[row] = 0;   // next call sees zeroed counters
}

// ---------------------------------------------------------------------------
extern "C" void kernel_launch(void* const* d_in, const int* in_sizes, int n_in,
                              void* d_out, int out_size) {
    const float* A     = (const float*)d_in[0];
    const float* Noise = (const float*)d_in[1];
    float* out = (float*)d_out;

    k_topk  <<<ROWS, 256>>>(A, Noise);
    k_deg   <<<(ROWS * 32 + 255) / 256, 256>>>();
    k_writer<<<ROWS, 256>>>(out);
}